// round 12
// baseline (speedup 1.0000x reference)
#include <cuda_runtime.h>
#include <cstdint>

// Problem constants (fixed by the dataset problem)
#define B_      256
#define D_      8192
#define S_      8
#define W_      4
#define NSLOTS_ 2048
#define SLEN_   3   // state_len = W-1

#define SLOT_BYTES    (D_ * SLEN_ * 4)            // 98304 bytes per slot
#define CHUNK_BYTES   12288                       // 12KB chunks
#define PARTS_PER_SLOT (SLOT_BYTES / CHUNK_BYTES) // 8
#define TOTAL_CHUNKS  (NSLOTS_ * PARTS_PER_SLOT)  // 16384
#define NUM_BLOCKS    (B_ * D_ / 256)             // 8192: each block = conv(256 rows) + 2 copy chunks
#define SMEM_BYTES    (16 + 2 * CHUNK_BYTES)      // [0:8) mbarrier, [16:...) two chunk buffers

// Locked-in findings (measured on GB300, this problem):
//  * role mixing per SM is worth ~4us vs phase-segregated launches.
//  * smem must not push blocks/SM below the reg-cap of 8 (R8: -3.4us at 6).
//    Here: 24.6KB x 8 = 197KB < 228KB; __launch_bounds__(256,8) pins regs<=32.
//  * cache hints (__ldcs/__stcs) cost ~0.8us — default policy only.
//  * cache_indices is int32 (R1: int64 cast -> illegal access).

__device__ __forceinline__ uint32_t smem_u32(const void* p) {
    uint32_t a;
    asm("{ .reg .u64 t; cvta.to.shared.u64 t, %1; cvt.u32.u64 %0, t; }" : "=r"(a) : "l"(p));
    return a;
}

// ---------------------------------------------------------------------------
// Single fused kernel, merged roles: every block does conv for 256 (b,d) rows
// AND copies two 12KB chunks of the untouched-slot state region.
// Pipeline per block (no __syncthreads anywhere):
//   1. warp0: membership tests, tid0 issues bulk-async LOADS (global->smem)
//   2. all 256 threads: conv + residual + fresh-state write  (hides TMA load)
//   3. tid0: mbarrier wait (already complete), bulk-async STORES, wait_group
// ---------------------------------------------------------------------------
__global__ void __launch_bounds__(256, 8)
k_main(const float* __restrict__ x,
       const float* __restrict__ weight,
       const float* __restrict__ conv_states,
       const int* __restrict__ cache_idx,
       const int* __restrict__ res_p,
       const int* __restrict__ pad_p,
       float* __restrict__ out,
       float* __restrict__ out_states) {
    extern __shared__ char smem[];
    const int tid = threadIdx.x;

    // Copy chunks owned by this block
    const int chunk0 = 2 * blockIdx.x;
    const int chunk1 = chunk0 + 1;
    const int slot0  = chunk0 >> 3;   // PARTS_PER_SLOT = 8
    const int slot1  = chunk1 >> 3;

    bool hit0 = false, hit1 = false;  // slot in cache_indices -> skip copy
    uint32_t sbase = 0;

    // ---- phase 1: warp0 membership + TMA load issue ----
    if (tid < 32) {
        const int4* p4 = reinterpret_cast<const int4*>(cache_idx);
        int4 a  = p4[tid];
        int4 b4 = p4[tid + 32];
        int pad = *pad_p;
        bool h0 =
            ((a.x  == slot0) & (a.x  != pad)) | ((a.y  == slot0) & (a.y  != pad)) |
            ((a.z  == slot0) & (a.z  != pad)) | ((a.w  == slot0) & (a.w  != pad)) |
            ((b4.x == slot0) & (b4.x != pad)) | ((b4.y == slot0) & (b4.y != pad)) |
            ((b4.z == slot0) & (b4.z != pad)) | ((b4.w == slot0) & (b4.w != pad));
        bool h1 =
            ((a.x  == slot1) & (a.x  != pad)) | ((a.y  == slot1) & (a.y  != pad)) |
            ((a.z  == slot1) & (a.z  != pad)) | ((a.w  == slot1) & (a.w  != pad)) |
            ((b4.x == slot1) & (b4.x != pad)) | ((b4.y == slot1) & (b4.y != pad)) |
            ((b4.z == slot1) & (b4.z != pad)) | ((b4.w == slot1) & (b4.w != pad));
        hit0 = __any_sync(0xffffffffu, h0);
        hit1 = __any_sync(0xffffffffu, h1);

        if (tid == 0) {
            sbase = smem_u32(smem);
            uint32_t mbar = sbase;
            uint32_t nbytes = (hit0 ? 0u : CHUNK_BYTES) + (hit1 ? 0u : CHUNK_BYTES);
            if (nbytes) {
                asm volatile("mbarrier.init.shared.b64 [%0], 1;" :: "r"(mbar) : "memory");
                asm volatile("fence.proxy.async.shared::cta;" ::: "memory");
                asm volatile("mbarrier.arrive.expect_tx.shared.b64 _, [%0], %1;"
                             :: "r"(mbar), "r"(nbytes) : "memory");
                if (!hit0) {
                    const char* src = (const char*)conv_states + (size_t)chunk0 * CHUNK_BYTES;
                    asm volatile("cp.async.bulk.shared::cluster.global.mbarrier::complete_tx::bytes "
                                 "[%0], [%1], %2, [%3];"
                                 :: "r"(sbase + 16), "l"(src), "r"((uint32_t)CHUNK_BYTES), "r"(mbar)
                                 : "memory");
                }
                if (!hit1) {
                    const char* src = (const char*)conv_states + (size_t)chunk1 * CHUNK_BYTES;
                    asm volatile("cp.async.bulk.shared::cluster.global.mbarrier::complete_tx::bytes "
                                 "[%0], [%1], %2, [%3];"
                                 :: "r"(sbase + 16 + CHUNK_BYTES), "l"(src),
                                    "r"((uint32_t)CHUNK_BYTES), "r"(mbar)
                                 : "memory");
                }
            }
        }
    }

    // ---- phase 2: conv + residual + fresh-state write (all 256 threads) ----
    {
        int t = blockIdx.x * 256 + tid;      // 0 .. B*D-1
        int d = t & (D_ - 1);
        int b = blockIdx.x >> 5;             // 32 blocks per batch row

        int slot = cache_idx[b];
        int pad  = *pad_p;
        bool valid = (slot != pad) && (slot >= 0) && (slot < NSLOTS_);
        int safe = valid ? slot : 0;

        const float* sp = conv_states + (size_t)safe * (D_ * SLEN_) + (size_t)d * SLEN_;
        float c0 = sp[0], c1 = sp[1], c2 = sp[2];

        const float4* xp = reinterpret_cast<const float4*>(x + (size_t)t * S_);
        float4 xa = xp[0];
        float4 xb = xp[1];

        float4 wv = reinterpret_cast<const float4*>(weight)[d];

        float c[11] = {c0, c1, c2, xa.x, xa.y, xa.z, xa.w, xb.x, xb.y, xb.z, xb.w};
        float res = (*res_p != 0) ? 1.0f : 0.0f;

        float o[8];
        #pragma unroll
        for (int s = 0; s < 8; s++) {
            float acc = res * c[s + 3];
            acc = fmaf(c[s + 3], wv.w, acc);
            acc = fmaf(c[s + 2], wv.z, acc);
            acc = fmaf(c[s + 1], wv.y, acc);
            acc = fmaf(c[s + 0], wv.x, acc);
            o[s] = acc;
        }

        float4* op = reinterpret_cast<float4*>(out + (size_t)t * S_);
        op[0] = make_float4(o[0], o[1], o[2], o[3]);
        op[1] = make_float4(o[4], o[5], o[6], o[7]);

        if (valid) {
            float* np = out_states + (size_t)slot * (D_ * SLEN_) + (size_t)d * SLEN_;
            np[0] = c[8];
            np[1] = c[9];
            np[2] = c[10];
        }
    }

    // ---- phase 3: tid0 waits (load long since done) and issues bulk stores ----
    if (tid == 0 && (!hit0 || !hit1)) {
        uint32_t mbar = sbase;
        asm volatile(
            "{\n\t"
            ".reg .pred P;\n\t"
            "WL_%=:\n\t"
            "mbarrier.try_wait.parity.shared.b64 P, [%0], 0, 0x989680;\n\t"
            "@P bra WD_%=;\n\t"
            "bra WL_%=;\n\t"
            "WD_%=:\n\t"
            "}" :: "r"(mbar) : "memory");
        if (!hit0) {
            char* dst = (char*)out_states + (size_t)chunk0 * CHUNK_BYTES;
            asm volatile("cp.async.bulk.global.shared::cta.bulk_group [%0], [%1], %2;"
                         :: "l"(dst), "r"(sbase + 16), "r"((uint32_t)CHUNK_BYTES) : "memory");
        }
        if (!hit1) {
            char* dst = (char*)out_states + (size_t)chunk1 * CHUNK_BYTES;
            asm volatile("cp.async.bulk.global.shared::cta.bulk_group [%0], [%1], %2;"
                         :: "l"(dst), "r"(sbase + 16 + CHUNK_BYTES), "r"((uint32_t)CHUNK_BYTES)
                         : "memory");
        }
        asm volatile("cp.async.bulk.commit_group;" ::: "memory");
        asm volatile("cp.async.bulk.wait_group 0;" ::: "memory");
    }
}

// ---------------------------------------------------------------------------
// Launch — single kernel, single graph node.
// Inputs: [0]=x f32, [1]=weight f32, [2]=conv_states f32,
//         [3]=cache_indices int32, [4]=residual_connection, [5]=pad_slot_id
// Output: [out (B*D*S) | new_conv_states (NSLOTS*D*SLEN)] as f32
// ---------------------------------------------------------------------------
extern "C" void kernel_launch(void* const* d_in, const int* in_sizes, int n_in,
                              void* d_out, int out_size) {
    const float* x   = (const float*)d_in[0];
    const float* wgt = (const float*)d_in[1];
    const float* st  = (const float*)d_in[2];
    const int*   idx = (const int*)d_in[3];
    const int*   res = (const int*)d_in[4];
    const int*   pad = (const int*)d_in[5];

    float* out        = (float*)d_out;
    float* out_states = out + (size_t)B_ * D_ * S_;

    k_main<<<NUM_BLOCKS, 256, SMEM_BYTES>>>(x, wgt, st, idx, res, pad, out, out_states);
}

// round 13
// speedup vs baseline: 1.0163x; 1.0163x over previous
#include <cuda_runtime.h>
#include <cstdint>

// Problem constants (fixed by the dataset problem)
#define B_      256
#define D_      8192
#define S_      8
#define W_      4
#define NSLOTS_ 2048
#define SLEN_   3   // state_len = W-1

#define SLOT_BYTES    (D_ * SLEN_ * 4)           // 98304 bytes per slot
#define CHUNK_BYTES   16384
#define COPY_PARTS    (SLOT_BYTES / CHUNK_BYTES) // 6
#define CONV_BLOCKS   (B_ * D_ / 256)            // 8192 (32 blocks per batch row)
#define COPY_BLOCKS   (NSLOTS_ * COPY_PARTS)     // 12288
#define TOTAL_BLOCKS  (CONV_BLOCKS + COPY_BLOCKS) // 20480 = 4096 groups of 5
#define SMEM_BYTES    (CHUNK_BYTES + 16)         // [0:8) mbarrier, [16:+CHUNK) data

// FINAL configuration — full experiment matrix (GB300, this problem):
//  * 2 conv : 3 copy interleave per 5 blocks: 75.6/76.0us kernel (best, 2x reproduced)
//  * phase-segregated launch: 79.0us (loses ~3.5us)
//  * 32KB TMA chunks: 79.0us (smem pushes blocks/SM 8->6)
//  * __ldcs/__stcs hints: 76.4us (perturbs DRAM sector scheduling)
//  * merged conv+copy blocks: 78.0us (store stream turns on too late per block)
//  * cache_indices is int32 (R1: int64 cast -> illegal access; JAX x64-off
//    downgrades astype(int64) to int32).
// Mandatory traffic = 536MB; this kernel moves it at ~7.1TB/s app-side
// (80.7% DRAM) — at the mixed-RW ceiling for this access pattern.

__device__ __forceinline__ uint32_t smem_u32(const void* p) {
    uint32_t a;
    asm("{ .reg .u64 t; cvta.to.shared.u64 t, %1; cvt.u32.u64 %0, t; }" : "=r"(a) : "l"(p));
    return a;
}

// ---------------------------------------------------------------------------
// Single fused kernel, interleaved roles (2 conv : 3 copy per group of 5,
// matching 8192:12288 exactly). Copy = 16KB bulk-async chunks (TMA engine).
// Default cache policy everywhere.
// ---------------------------------------------------------------------------
__global__ void __launch_bounds__(256)
k_main(const float* __restrict__ x,
       const float* __restrict__ weight,
       const float* __restrict__ conv_states,
       const int* __restrict__ cache_idx,
       const int* __restrict__ res_p,
       const int* __restrict__ pad_p,
       float* __restrict__ out,
       float* __restrict__ out_states) {
    extern __shared__ char smem[];
    const int tid = threadIdx.x;

    const int group = blockIdx.x / 5;
    const int r     = blockIdx.x - group * 5;

    if (r < 2) {
        // ---- conv + residual + fresh-state write (conv_id in [0, 8192)) ----
        int cid = group * 2 + r;
        int t = cid * 256 + tid;             // 0 .. B*D-1
        int d = t & (D_ - 1);
        int b = cid >> 5;                    // 32 blocks per batch row

        int slot = cache_idx[b];
        int pad  = *pad_p;
        bool valid = (slot != pad) && (slot >= 0) && (slot < NSLOTS_);
        int safe = valid ? slot : 0;

        const float* sp = conv_states + (size_t)safe * (D_ * SLEN_) + (size_t)d * SLEN_;
        float c0 = sp[0], c1 = sp[1], c2 = sp[2];

        const float4* xp = reinterpret_cast<const float4*>(x + (size_t)t * S_);
        float4 xa = xp[0];
        float4 xb = xp[1];

        float4 wv = reinterpret_cast<const float4*>(weight)[d];

        float c[11] = {c0, c1, c2, xa.x, xa.y, xa.z, xa.w, xb.x, xb.y, xb.z, xb.w};
        float res = (*res_p != 0) ? 1.0f : 0.0f;

        float o[8];
        #pragma unroll
        for (int s = 0; s < 8; s++) {
            float acc = res * c[s + 3];
            acc = fmaf(c[s + 3], wv.w, acc);
            acc = fmaf(c[s + 2], wv.z, acc);
            acc = fmaf(c[s + 1], wv.y, acc);
            acc = fmaf(c[s + 0], wv.x, acc);
            o[s] = acc;
        }

        float4* op = reinterpret_cast<float4*>(out + (size_t)t * S_);
        op[0] = make_float4(o[0], o[1], o[2], o[3]);
        op[1] = make_float4(o[4], o[5], o[6], o[7]);

        if (valid) {
            float* np = out_states + (size_t)slot * (D_ * SLEN_) + (size_t)d * SLEN_;
            np[0] = c[8];
            np[1] = c[9];
            np[2] = c[10];
        }
    } else {
        // ---- copy untouched slots via bulk-async engine (copy_id in [0,12288)) ----
        if (tid >= 32) return;               // warp0 only
        int cb   = group * 3 + (r - 2);
        int slot = cb / COPY_PARTS;
        int part = cb - slot * COPY_PARTS;

        // Membership: 256 indices as 64 int4; each lane checks 2 int4 (8 ints).
        const int4* p4 = reinterpret_cast<const int4*>(cache_idx);
        int4 a  = p4[tid];
        int4 b4 = p4[tid + 32];
        int pad = *pad_p;
        bool hit =
            ((a.x  == slot) & (a.x  != pad)) | ((a.y  == slot) & (a.y  != pad)) |
            ((a.z  == slot) & (a.z  != pad)) | ((a.w  == slot) & (a.w  != pad)) |
            ((b4.x == slot) & (b4.x != pad)) | ((b4.y == slot) & (b4.y != pad)) |
            ((b4.z == slot) & (b4.z != pad)) | ((b4.w == slot) & (b4.w != pad));
        if (__any_sync(0xffffffffu, hit)) return;  // slot gets fresh state from conv

        if (tid == 0) {
            uint32_t sbase = smem_u32(smem);
            uint32_t mbar  = sbase;          // 8B mbarrier at offset 0
            uint32_t sdata = sbase + 16;     // 16B-aligned data region

            size_t off = (size_t)slot * SLOT_BYTES + (size_t)part * CHUNK_BYTES;
            const char* src = (const char*)conv_states + off;
            char*       dst = (char*)out_states + off;

            asm volatile("mbarrier.init.shared.b64 [%0], 1;" :: "r"(mbar) : "memory");
            asm volatile("fence.proxy.async.shared::cta;" ::: "memory");
            asm volatile("mbarrier.arrive.expect_tx.shared.b64 _, [%0], %1;"
                         :: "r"(mbar), "r"((uint32_t)CHUNK_BYTES) : "memory");
            asm volatile("cp.async.bulk.shared::cluster.global.mbarrier::complete_tx::bytes "
                         "[%0], [%1], %2, [%3];"
                         :: "r"(sdata), "l"(src), "r"((uint32_t)CHUNK_BYTES), "r"(mbar)
                         : "memory");
            // wait for the load (parity 0)
            asm volatile(
                "{\n\t"
                ".reg .pred P;\n\t"
                "WL_%=:\n\t"
                "mbarrier.try_wait.parity.shared.b64 P, [%0], 0, 0x989680;\n\t"
                "@P bra WD_%=;\n\t"
                "bra WL_%=;\n\t"
                "WD_%=:\n\t"
                "}" :: "r"(mbar) : "memory");
            // store smem -> global via bulk engine
            asm volatile("cp.async.bulk.global.shared::cta.bulk_group [%0], [%1], %2;"
                         :: "l"(dst), "r"(sdata), "r"((uint32_t)CHUNK_BYTES) : "memory");
            asm volatile("cp.async.bulk.commit_group;" ::: "memory");
            asm volatile("cp.async.bulk.wait_group 0;" ::: "memory");
        }
    }
}

// ---------------------------------------------------------------------------
// Launch — single kernel, single graph node.
// Inputs: [0]=x f32, [1]=weight f32, [2]=conv_states f32,
//         [3]=cache_indices int32, [4]=residual_connection, [5]=pad_slot_id
// Output: [out (B*D*S) | new_conv_states (NSLOTS*D*SLEN)] as f32
// ---------------------------------------------------------------------------
extern "C" void kernel_launch(void* const* d_in, const int* in_sizes, int n_in,
                              void* d_out, int out_size) {
    const float* x   = (const float*)d_in[0];
    const float* wgt = (const float*)d_in[1];
    const float* st  = (const float*)d_in[2];
    const int*   idx = (const int*)d_in[3];
    const int*   res = (const int*)d_in[4];
    const int*   pad = (const int*)d_in[5];

    float* out        = (float*)d_out;
    float* out_states = out + (size_t)B_ * D_ * S_;

    k_main<<<TOTAL_BLOCKS, 256, SMEM_BYTES>>>(x, wgt, st, idx, res, pad, out, out_states);
}